// round 13
// baseline (speedup 1.0000x reference)
#include <cuda_runtime.h>
#include <cuda_fp16.h>
#include <cuda_bf16.h>

#define B_  16
#define LQ  256
#define LK  256
#define QD  256
#define HD  128
#define VD  128
#define KT  4     // k-rows per CTA; every warp computes all 4 for its 64-q strip

// f16 projected q/k, TRANSPOSED per batch: [b][h][q] / [b][h][k]  (2MB: L2-resident)
__device__ __half g_qpT[B_ * HD * LQ];
__device__ __half g_kpT[B_ * HD * LK];

namespace {  // internal linkage: immune to cuda_fp16.hpp name collisions

__device__ __forceinline__ __half2 tanh_h2_(__half2 x) {
    unsigned xo, xi = *(unsigned*)&x;
    asm("tanh.approx.f16x2 %0, %1;" : "=r"(xo) : "r"(xi));
    return *(__half2*)&xo;
}
__device__ __forceinline__ unsigned long long pk2_(float lo, float hi) {
    unsigned long long r;
    asm("mov.b64 %0, {%1, %2};" : "=l"(r) : "f"(lo), "f"(hi));
    return r;
}
__device__ __forceinline__ void upk2_(unsigned long long v, float& lo, float& hi) {
    asm("mov.b64 {%0, %1}, %2;" : "=f"(lo), "=f"(hi) : "l"(v));
}
__device__ __forceinline__ void fma2_(unsigned long long& d, unsigned long long a,
                                      unsigned long long b) {
    asm("fma.rn.f32x2 %0, %1, %2, %0;" : "+l"(d) : "l"(a), "l"(b));
}

}  // namespace

// ============================================================================
// Kernel 1: qp = query @ Wq, kp = key @ Wk  (fp32 math, f32x2 FFMA, epilogue
// stores f16 TRANSPOSED [b][h][row]). BM=16, BN=128, BK=32, 256 threads,
// thread tile 2 rows x 4 cols. grid (256,2) = 512 CTAs (~3.5/SM).
// ============================================================================
__global__ __launch_bounds__(256) void proj_kernel(
    const float* __restrict__ q_in, const float* __restrict__ k_in,
    const float* __restrict__ Wq,   const float* __restrict__ Wk)
{
    const float* X  = blockIdx.y ? k_in : q_in;
    const float* W  = blockIdx.y ? Wk : Wq;
    __half*      YT = blockIdx.y ? g_kpT : g_qpT;

    __shared__ __align__(16) float As[32][18];   // [k][row], 16 rows + pad
    __shared__ __align__(16) float Bs[32][128];  // [k][h]

    const int t  = threadIdx.x;
    const int tx = t & 31;          // col group (4 h)
    const int ty = t >> 5;          // row group (2 rows), 0..7
    const int r0 = blockIdx.x * 16;

    unsigned long long acc[4];      // rowpair x 4 cols
    #pragma unroll
    for (int c = 0; c < 4; c++) acc[c] = 0ull;

    for (int kb = 0; kb < QD; kb += 32) {
        __syncthreads();
        if (t < 128) {   // A tile 16x32 transposed: one float4 per thread
            int kk4 = t & 7, r = t >> 3;     // r 0..15
            float4 a4 = *(const float4*)&X[(r0 + r) * QD + kb + kk4 * 4];
            As[kk4 * 4 + 0][r] = a4.x;
            As[kk4 * 4 + 1][r] = a4.y;
            As[kk4 * 4 + 2][r] = a4.z;
            As[kk4 * 4 + 3][r] = a4.w;
        }
        {   // B tile 32x128: 4 float4 per thread
            int h4 = t & 31, kk = t >> 5;
            #pragma unroll
            for (int j = 0; j < 4; j++)
                *(float4*)&Bs[kk + 8 * j][h4 * 4] =
                    *(const float4*)&W[(kb + kk + 8 * j) * HD + h4 * 4];
        }
        __syncthreads();
        #pragma unroll
        for (int kk = 0; kk < 32; kk++) {
            float2 a  = *(const float2*)&As[kk][ty * 2];   // bcast (2 rows)
            float4 bv = *(const float4*)&Bs[kk][tx * 4];   // lane-strided
            unsigned long long ap = pk2_(a.x, a.y);
            unsigned long long bb[4] = { pk2_(bv.x, bv.x), pk2_(bv.y, bv.y),
                                         pk2_(bv.z, bv.z), pk2_(bv.w, bv.w) };
            #pragma unroll
            for (int c = 0; c < 4; c++) fma2_(acc[c], ap, bb[c]);
        }
    }

    const int bb   = r0 / LQ;
    const int qloc = (r0 % LQ) + ty * 2;
    #pragma unroll
    for (int c = 0; c < 4; c++) {
        int h = tx * 4 + c;
        float lo, hi;
        upk2_(acc[c], lo, hi);
        __half2 p = __floats2half2_rn(lo, hi);
        *(unsigned*)&YT[(bb * HD + h) * LQ + qloc] = *(unsigned*)&p;
    }
}

// ============================================================================
// Kernel 2: scores + softmax + context. grid = 1024 CTAs, 128 threads.
// Entry: stage kvs4[128] (4-dup kp) + vdup[128] (dup f16 v) ONCE (1 barrier).
// Phase B: warp w owns q-strip [64w,64w+64), lane = 2 q; all 4 k-rows.
//   Per h: prefetched LDG.32 qp (L2) + LDS.128 kvs4 bcast + LDS.32 vdup bcast
//   -> 4 HADD2 + 4 tanh.f16x2 + 4 HFMA2. 128 LDG/warp total (was 384).
//   qp double-buffered in 8-h register stages; f16 chains flushed every 8 h.
// Phase C: scores -> S smem, barrier, warp w softmaxes k-row w.
// Phase D: value staged as f16 (8KB), warp = (k-pair, vd-half). smem 14.5KB.
// ============================================================================
__global__ __launch_bounds__(128, 8) void attn_kernel(
    const float* __restrict__ value, const float* __restrict__ vvec,
    float* __restrict__ ctx, float* __restrict__ attn)
{
    const int b  = blockIdx.x >> 6;          // 64 k-tiles per batch
    const int k0 = (blockIdx.x & 63) * KT;

    __shared__ __align__(16) float    S[4 * 256];        // 4096 B
    __shared__ __align__(16) unsigned val16[32 * 64];    // 8192 B
    __shared__ __align__(16) uint4    kvs4[HD];          // 2048 B
    __shared__            unsigned    vdup[HD];          // 512 B

    const int t    = threadIdx.x;
    const int w    = t >> 5;
    const int lane = t & 31;
    const int qidx = w * 32 + lane;          // q = 2*qidx, 2*qidx+1

    const __half* qb = g_qpT + (size_t)b * HD * LQ + 2 * qidx;
    const __half* kb = g_kpT + (size_t)b * HD * LK + k0;

    // ---- Entry staging: kp (4-dup) + v (dup f16), h = t ----
    {
        uint2 kk = *(const uint2*)(kb + t * LK);
        __half2 kp01 = *(__half2*)&kk.x;
        __half2 kp23 = *(__half2*)&kk.y;
        __half2 d0 = __low2half2(kp01), d1 = __high2half2(kp01);
        __half2 d2 = __low2half2(kp23), d3 = __high2half2(kp23);
        kvs4[t] = make_uint4(*(unsigned*)&d0, *(unsigned*)&d1,
                             *(unsigned*)&d2, *(unsigned*)&d3);
        __half2 vd = __float2half2_rn(vvec[t]);
        vdup[t] = *(unsigned*)&vd;
    }
    __syncthreads();

    float accf[4][2];
    #pragma unroll
    for (int k = 0; k < 4; k++) { accf[k][0] = 0.f; accf[k][1] = 0.f; }

    // ---- Phase B: double-buffered qp prefetch, 8-h stages ----
    unsigned qb0[8], qb1[8];
    #pragma unroll
    for (int j = 0; j < 8; j++)
        qb0[j] = *(const unsigned*)(qb + j * LQ);

    #pragma unroll
    for (int h16 = 0; h16 < HD; h16 += 16) {
        #pragma unroll
        for (int j = 0; j < 8; j++)
            qb1[j] = *(const unsigned*)(qb + (h16 + 8 + j) * LQ);
        // compute stage A (h16 .. h16+7) from qb0
        {
            __half2 ae[4], ao[4];
            #pragma unroll
            for (int k = 0; k < 4; k++) { ae[k] = __float2half2_rn(0.f); ao[k] = ae[k]; }
            #pragma unroll
            for (int j = 0; j < 8; j++) {
                int h = h16 + j;
                uint4 kv = kvs4[h];                      // bcast
                unsigned vu = vdup[h];                   // bcast
                __half2 q2 = *(__half2*)&qb0[j];
                __half2 vd = *(__half2*)&vu;
                __half2 t0 = tanh_h2_(__hadd2(q2, *(__half2*)&kv.x));
                __half2 t1 = tanh_h2_(__hadd2(q2, *(__half2*)&kv.y));
                __half2 t2 = tanh_h2_(__hadd2(q2, *(__half2*)&kv.z));
                __half2 t3 = tanh_h2_(__hadd2(q2, *(__half2*)&kv.w));
                if (j & 1) {
                    ao[0] = __hfma2(t0, vd, ao[0]); ao[1] = __hfma2(t1, vd, ao[1]);
                    ao[2] = __hfma2(t2, vd, ao[2]); ao[3] = __hfma2(t3, vd, ao[3]);
                } else {
                    ae[0] = __hfma2(t0, vd, ae[0]); ae[1] = __hfma2(t1, vd, ae[1]);
                    ae[2] = __hfma2(t2, vd, ae[2]); ae[3] = __hfma2(t3, vd, ae[3]);
                }
            }
            #pragma unroll
            for (int k = 0; k < 4; k++) {
                float2 f2 = __half22float2(__hadd2(ae[k], ao[k]));
                accf[k][0] += f2.x; accf[k][1] += f2.y;
            }
        }
        if (h16 + 16 < HD) {
            #pragma unroll
            for (int j = 0; j < 8; j++)
                qb0[j] = *(const unsigned*)(qb + (h16 + 16 + j) * LQ);
        }
        // compute stage B (h16+8 .. h16+15) from qb1
        {
            __half2 ae[4], ao[4];
            #pragma unroll
            for (int k = 0; k < 4; k++) { ae[k] = __float2half2_rn(0.f); ao[k] = ae[k]; }
            #pragma unroll
            for (int j = 0; j < 8; j++) {
                int h = h16 + 8 + j;
                uint4 kv = kvs4[h];
                unsigned vu = vdup[h];
                __half2 q2 = *(__half2*)&qb1[j];
                __half2 vd = *(__half2*)&vu;
                __half2 t0 = tanh_h2_(__hadd2(q2, *(__half2*)&kv.x));
                __half2 t1 = tanh_h2_(__hadd2(q2, *(__half2*)&kv.y));
                __half2 t2 = tanh_h2_(__hadd2(q2, *(__half2*)&kv.z));
                __half2 t3 = tanh_h2_(__hadd2(q2, *(__half2*)&kv.w));
                if (j & 1) {
                    ao[0] = __hfma2(t0, vd, ao[0]); ao[1] = __hfma2(t1, vd, ao[1]);
                    ao[2] = __hfma2(t2, vd, ao[2]); ao[3] = __hfma2(t3, vd, ao[3]);
                } else {
                    ae[0] = __hfma2(t0, vd, ae[0]); ae[1] = __hfma2(t1, vd, ae[1]);
                    ae[2] = __hfma2(t2, vd, ae[2]); ae[3] = __hfma2(t3, vd, ae[3]);
                }
            }
            #pragma unroll
            for (int k = 0; k < 4; k++) {
                float2 f2 = __half22float2(__hadd2(ae[k], ao[k]));
                accf[k][0] += f2.x; accf[k][1] += f2.y;
            }
        }
    }

    // ---- Phase C: softmax over q (scores -> S, warp w reduces k-row w) ----
    #pragma unroll
    for (int k = 0; k < 4; k++)
        *(float2*)&S[k * 256 + 2 * qidx] = make_float2(accf[k][0], accf[k][1]);
    __syncthreads();
    {
        float vals[8], m = -1e30f;
        #pragma unroll
        for (int i = 0; i < 8; i++) {
            vals[i] = S[w * 256 + lane + 32 * i];
            m = fmaxf(m, vals[i]);
        }
        #pragma unroll
        for (int o = 16; o > 0; o >>= 1)
            m = fmaxf(m, __shfl_xor_sync(0xffffffffu, m, o));
        float s = 0.f;
        #pragma unroll
        for (int i = 0; i < 8; i++) { vals[i] = __expf(vals[i] - m); s += vals[i]; }
        #pragma unroll
        for (int o = 16; o > 0; o >>= 1)
            s += __shfl_xor_sync(0xffffffffu, s, o);
        float inv = 1.0f / s;
        #pragma unroll
        for (int i = 0; i < 8; i++)
            S[w * 256 + lane + 32 * i] = vals[i] * inv;
        __syncwarp();
        float* arow = attn + (size_t)(b * LK + k0 + w) * LQ;
        #pragma unroll
        for (int j = 0; j < 2; j++)
            *(float4*)&arow[lane * 4 + 128 * j] =
                *(const float4*)&S[w * 256 + lane * 4 + 128 * j];
    }

    // ---- Phase D: ctx = P @ value (value f16 in smem). ----
    const int kp2  = (w & 1) * 2;
    const int voff = (w >> 1) * 32;
    float2 c0 = make_float2(0.f, 0.f);
    float2 c1 = make_float2(0.f, 0.f);
    const float* val_b = value + (size_t)b * LQ * VD;
    for (int qt = 0; qt < 8; qt++) {
        __syncthreads();                     // P writes / prior tile reads done
        #pragma unroll
        for (int j = 0; j < 8; j++) {        // stage 32x128 value tile as f16
            int idx = t + 128 * j;
            int q = idx >> 5, c4 = idx & 31;
            float4 v4 = *(const float4*)&val_b[(qt * 32 + q) * VD + c4 * 4];
            __half2 h0 = __floats2half2_rn(v4.x, v4.y);
            __half2 h1 = __floats2half2_rn(v4.z, v4.w);
            *(uint2*)&val16[q * 64 + c4 * 2] =
                make_uint2(*(unsigned*)&h0, *(unsigned*)&h1);
        }
        __syncthreads();
        #pragma unroll
        for (int q4 = 0; q4 < 8; q4++) {
            float4 P0 = *(const float4*)&S[(kp2)     * 256 + qt * 32 + q4 * 4];
            float4 P1 = *(const float4*)&S[(kp2 + 1) * 256 + qt * 32 + q4 * 4];
            const float pa0[4] = { P0.x, P0.y, P0.z, P0.w };
            const float pa1[4] = { P1.x, P1.y, P1.z, P1.w };
            #pragma unroll
            for (int u = 0; u < 4; u++) {
                unsigned hv = val16[(q4 * 4 + u) * 64 + voff + lane];
                float2 f = __half22float2(*(__half2*)&hv);
                c0.x += pa0[u] * f.x; c0.y += pa0[u] * f.y;
                c1.x += pa1[u] * f.x; c1.y += pa1[u] * f.y;
            }
        }
    }
    const int vh = voff * 2;
    *(float2*)&ctx[(size_t)(b * LK + k0 + kp2)     * VD + vh + 2 * lane] = c0;
    *(float2*)&ctx[(size_t)(b * LK + k0 + kp2 + 1) * VD + vh + 2 * lane] = c1;
}

// ============================================================================
// Launch: inputs: query, key, value, Wq, Wk, v
// d_out = context [B,LK,VD] followed by attention [B,LK,LQ]
// ============================================================================
extern "C" void kernel_launch(void* const* d_in, const int* in_sizes, int n_in,
                              void* d_out, int out_size)
{
    const float* query = (const float*)d_in[0];
    const float* key_t = (const float*)d_in[1];
    const float* value = (const float*)d_in[2];
    const float* Wq    = (const float*)d_in[3];
    const float* Wk    = (const float*)d_in[4];
    const float* vvec  = (const float*)d_in[5];

    float* ctx  = (float*)d_out;
    float* attn = ctx + (size_t)B_ * LK * VD;

    dim3 g1((B_ * LQ) / 16, 2);          // 256 x 2 = 512 CTAs
    proj_kernel<<<g1, 256>>>(query, key_t, Wq, Wk);
    attn_kernel<<<B_ * (LK / KT), 128>>>(value, vvec, ctx, attn);
}

// round 15
// speedup vs baseline: 1.1873x; 1.1873x over previous
#include <cuda_runtime.h>
#include <cuda_fp16.h>
#include <cuda_bf16.h>

#define B_  16
#define LQ  256
#define LK  256
#define QD  256
#define HD  128
#define VD  128
#define KT  4     // k-rows per CTA; every warp computes all 4 for its 64-q strip

// v vector in __constant__ memory (uniform per h; populated per launch via
// cudaMemcpyToSymbolAsync -- device-to-device, graph-capturable).
__constant__ float c_vvec[HD];

// f16 projected q/k, TRANSPOSED per batch: [b][h][q] / [b][h][k]  (2MB: L2-resident)
__device__ __half g_qpT[B_ * HD * LQ];
__device__ __half g_kpT[B_ * HD * LK];
__device__ __half g_val16[B_ * LQ * VD];   // f16 copy of value (1MB)

namespace {  // internal linkage: immune to cuda_fp16.hpp name collisions

__device__ __forceinline__ __half2 tanh_h2_(__half2 x) {
    unsigned xo, xi = *(unsigned*)&x;
    asm("tanh.approx.f16x2 %0, %1;" : "=r"(xo) : "r"(xi));
    return *(__half2*)&xo;
}
__device__ __forceinline__ unsigned long long pk2_(float lo, float hi) {
    unsigned long long r;
    asm("mov.b64 %0, {%1, %2};" : "=l"(r) : "f"(lo), "f"(hi));
    return r;
}
__device__ __forceinline__ void upk2_(unsigned long long v, float& lo, float& hi) {
    asm("mov.b64 {%0, %1}, %2;" : "=f"(lo), "=f"(hi) : "l"(v));
}
__device__ __forceinline__ void fma2_(unsigned long long& d, unsigned long long a,
                                      unsigned long long b) {
    asm("fma.rn.f32x2 %0, %1, %2, %0;" : "+l"(d) : "l"(a), "l"(b));
}

}  // namespace

// ============================================================================
// Kernel 0: value f32 -> f16 (g_val16). 256 CTAs x 256 thr x 8 elems.
// ============================================================================
__global__ __launch_bounds__(256) void cvt_val_kernel(const float* __restrict__ v) {
    int i = (blockIdx.x * 256 + threadIdx.x) * 8;
    float4 a = *(const float4*)(v + i);
    float4 b = *(const float4*)(v + i + 4);
    __half2 h0 = __floats2half2_rn(a.x, a.y), h1 = __floats2half2_rn(a.z, a.w);
    __half2 h2 = __floats2half2_rn(b.x, b.y), h3 = __floats2half2_rn(b.z, b.w);
    *(uint4*)&g_val16[i] = make_uint4(*(unsigned*)&h0, *(unsigned*)&h1,
                                      *(unsigned*)&h2, *(unsigned*)&h3);
}

// ============================================================================
// Kernel 1: qp = query @ Wq, kp = key @ Wk  (fp32 math, f32x2 FFMA, epilogue
// stores f16 TRANSPOSED [b][h][row]). BM=32, BN=128, BK=32, 256 threads. (R12)
// ============================================================================
__global__ __launch_bounds__(256) void proj_kernel(
    const float* __restrict__ q_in, const float* __restrict__ k_in,
    const float* __restrict__ Wq,   const float* __restrict__ Wk)
{
    const float* X  = blockIdx.y ? k_in : q_in;
    const float* W  = blockIdx.y ? Wk : Wq;
    __half*      YT = blockIdx.y ? g_kpT : g_qpT;

    __shared__ __align__(16) float As[32][36];
    __shared__ __align__(16) float Bs[32][128];

    const int t  = threadIdx.x;
    const int tx = t & 31;
    const int ty = t >> 5;
    const int r0 = blockIdx.x * 32;

    unsigned long long acc[2][4];
    #pragma unroll
    for (int rp = 0; rp < 2; rp++)
        #pragma unroll
        for (int c = 0; c < 4; c++) acc[rp][c] = 0ull;

    for (int kb = 0; kb < QD; kb += 32) {
        __syncthreads();
        {   // A tile 32x32 transposed
            int kk4 = t & 7, r = t >> 3;
            float4 a4 = *(const float4*)&X[(r0 + r) * QD + kb + kk4 * 4];
            As[kk4 * 4 + 0][r] = a4.x;
            As[kk4 * 4 + 1][r] = a4.y;
            As[kk4 * 4 + 2][r] = a4.z;
            As[kk4 * 4 + 3][r] = a4.w;
        }
        {   // B tile 32x128
            int h4 = t & 31, kk = t >> 5;
            #pragma unroll
            for (int j = 0; j < 4; j++)
                *(float4*)&Bs[kk + 8 * j][h4 * 4] =
                    *(const float4*)&W[(kb + kk + 8 * j) * HD + h4 * 4];
        }
        __syncthreads();
        #pragma unroll
        for (int kk = 0; kk < 32; kk++) {
            float4 a  = *(const float4*)&As[kk][ty * 4];
            float4 bv = *(const float4*)&Bs[kk][tx * 4];
            unsigned long long ap0 = pk2_(a.x, a.y);
            unsigned long long ap1 = pk2_(a.z, a.w);
            unsigned long long bb[4] = { pk2_(bv.x, bv.x), pk2_(bv.y, bv.y),
                                         pk2_(bv.z, bv.z), pk2_(bv.w, bv.w) };
            #pragma unroll
            for (int c = 0; c < 4; c++) { fma2_(acc[0][c], ap0, bb[c]);
                                          fma2_(acc[1][c], ap1, bb[c]); }
        }
    }

    const int bb   = r0 / LQ;
    const int qloc = (r0 % LQ) + ty * 4;
    #pragma unroll
    for (int c = 0; c < 4; c++) {
        int h = tx * 4 + c;
        float r01lo, r01hi, r23lo, r23hi;
        upk2_(acc[0][c], r01lo, r01hi);
        upk2_(acc[1][c], r23lo, r23hi);
        __half2 p0 = __floats2half2_rn(r01lo, r01hi);
        __half2 p1 = __floats2half2_rn(r23lo, r23hi);
        uint2 out = make_uint2(*(unsigned*)&p0, *(unsigned*)&p1);
        *(uint2*)&YT[(bb * HD + h) * LQ + qloc] = out;
    }
}

// ============================================================================
// Kernel 2: scores + softmax + context. grid = 1024 CTAs, 128 threads.
// Phase B (R12, proven): no smem. Warp w owns q-strip [64w,64w+64), lane=2 q.
//   Per h: LDG.32 qp + LDG.64 kp (uniform) + LDC v ->
//   4 HADD2 + 4 tanh.f16x2 + 4 HFMA2 = 8 tanh; f16 chains flushed every 8 h.
// Phase C: scores->S f32, barrier, warp w softmaxes k-row w; writes attn
//   directly (STG.32) + f16 P copy into S16h for phase D.
// Phase D: BARRIER-FREE. Direct LDG of g_val16 (L2), f16 HFMA2 chains
//   (P dups via half-lane selectors), f32 flush every 8 q. smem = 6KB.
// ============================================================================
__global__ __launch_bounds__(128, 8) void attn_kernel(
    float* __restrict__ ctx, float* __restrict__ attn)
{
    const int b  = blockIdx.x >> 6;          // 64 k-tiles per batch
    const int k0 = (blockIdx.x & 63) * KT;

    __shared__ __align__(16) float  S[4 * 256];      // 4096 B (scores)
    __shared__ __align__(8)  __half S16h[4 * 256];   // 2048 B (P f16)

    const int t    = threadIdx.x;
    const int w    = t >> 5;
    const int lane = t & 31;
    const int qidx = w * 32 + lane;          // q = 2*qidx, 2*qidx+1

    const __half* qb = g_qpT + (size_t)b * HD * LQ + 2 * qidx;
    const __half* kb = g_kpT + (size_t)b * HD * LK + k0;

    float accf[4][2];
    #pragma unroll
    for (int k = 0; k < 4; k++) { accf[k][0] = 0.f; accf[k][1] = 0.f; }

    // ---- Phase B: scores, straight from gmem (L2-resident) ----
    #pragma unroll 2
    for (int h8 = 0; h8 < HD; h8 += 8) {
        unsigned qv[8]; uint2 kp[8];
        #pragma unroll
        for (int j = 0; j < 8; j++) {
            qv[j] = *(const unsigned*)(qb + (h8 + j) * LQ);   // lane-strided
            kp[j] = *(const uint2*)  (kb + (h8 + j) * LK);    // uniform
        }
        __half2 ae[4], ao[4];
        #pragma unroll
        for (int k = 0; k < 4; k++) { ae[k] = __float2half2_rn(0.f); ao[k] = ae[k]; }
        #pragma unroll
        for (int j = 0; j < 8; j++) {
            __half2 q2   = *(__half2*)&qv[j];
            __half2 kp01 = *(__half2*)&kp[j].x;
            __half2 kp23 = *(__half2*)&kp[j].y;
            __half2 vd   = __float2half2_rn(c_vvec[h8 + j]);
            __half2 t0 = tanh_h2_(__hadd2(q2, __low2half2(kp01)));
            __half2 t1 = tanh_h2_(__hadd2(q2, __high2half2(kp01)));
            __half2 t2 = tanh_h2_(__hadd2(q2, __low2half2(kp23)));
            __half2 t3 = tanh_h2_(__hadd2(q2, __high2half2(kp23)));
            if (j & 1) {
                ao[0] = __hfma2(t0, vd, ao[0]); ao[1] = __hfma2(t1, vd, ao[1]);
                ao[2] = __hfma2(t2, vd, ao[2]); ao[3] = __hfma2(t3, vd, ao[3]);
            } else {
                ae[0] = __hfma2(t0, vd, ae[0]); ae[1] = __hfma2(t1, vd, ae[1]);
                ae[2] = __hfma2(t2, vd, ae[2]); ae[3] = __hfma2(t3, vd, ae[3]);
            }
        }
        #pragma unroll
        for (int k = 0; k < 4; k++) {
            float2 f2 = __half22float2(__hadd2(ae[k], ao[k]));
            accf[k][0] += f2.x;
            accf[k][1] += f2.y;
        }
    }

    // ---- Phase C: softmax over q (scores -> S, warp w reduces k-row w) ----
    #pragma unroll
    for (int k = 0; k < 4; k++)
        *(float2*)&S[k * 256 + 2 * qidx] = make_float2(accf[k][0], accf[k][1]);
    __syncthreads();
    {
        float vals[8], m = -1e30f;
        #pragma unroll
        for (int i = 0; i < 8; i++) {
            vals[i] = S[w * 256 + lane + 32 * i];
            m = fmaxf(m, vals[i]);
        }
        #pragma unroll
        for (int o = 16; o > 0; o >>= 1)
            m = fmaxf(m, __shfl_xor_sync(0xffffffffu, m, o));
        float s = 0.f;
        #pragma unroll
        for (int i = 0; i < 8; i++) { vals[i] = __expf(vals[i] - m); s += vals[i]; }
        #pragma unroll
        for (int o = 16; o > 0; o >>= 1)
            s += __shfl_xor_sync(0xffffffffu, s, o);
        float inv = 1.0f / s;
        float* arow = attn + (size_t)(b * LK + k0 + w) * LQ;
        #pragma unroll
        for (int i = 0; i < 8; i++) {
            float p = vals[i] * inv;
            arow[lane + 32 * i] = p;                      // STG.32 coalesced
            S16h[w * 256 + lane + 32 * i] = __float2half(p);
        }
    }
    __syncthreads();                       // S16h visible to all warps

    // ---- Phase D: ctx = P @ value, barrier-free, f16 math ----
    const int kp2  = (w & 1) * 2;
    const int voff = (w >> 1) * 32;        // half2 column index
    const __half* vb = g_val16 + (size_t)b * LQ * VD + 2 * (voff + lane);
    float2 a0 = make_float2(0.f, 0.f), a1 = a0;
    #pragma unroll 2
    for (int q8 = 0; q8 < LQ; q8 += 8) {
        __half2 e0 = __float2half2_rn(0.f), o0 = e0, e1 = e0, o1 = e0;
        #pragma unroll
        for (int q4 = 0; q4 < 2; q4++) {
            int q = q8 + q4 * 4;
            uint2 pu0 = *(const uint2*)&S16h[kp2 * 256 + q];        // bcast
            uint2 pu1 = *(const uint2*)&S16h[(kp2 + 1) * 256 + q];  // bcast
            __half2 p0ab = *(__half2*)&pu0.x, p0cd = *(__half2*)&pu0.y;
            __half2 p1ab = *(__half2*)&pu1.x, p1cd = *(__half2*)&pu1.y;
            __half2 v0 = *(const __half2*)(vb + (q + 0) * VD);
            __half2 v1 = *(const __half2*)(vb + (q + 1) * VD);
            __half2 v2 = *(const __half2*)(vb + (q + 2) * VD);
            __half2 v3 = *(const __half2*)(vb + (q + 3) * VD);
            e0 = __hfma2(v0, __low2half2(p0ab),  e0);
            e1 = __hfma2(v0, __low2half2(p1ab),  e1);
            o0 = __hfma2(v1, __high2half2(p0ab), o0);
            o1 = __hfma2(v1, __high2half2(p1ab), o1);
            e0 = __hfma2(v2, __low2half2(p0cd),  e0);
            e1 = __hfma2(v2, __low2half2(p1cd),  e1);
            o0 = __hfma2(v3, __high2half2(p0cd), o0);
            o1 = __hfma2(v3, __high2half2(p1cd), o1);
        }
        float2 f0 = __half22float2(__hadd2(e0, o0));
        float2 f1 = __half22float2(__hadd2(e1, o1));
        a0.x += f0.x; a0.y += f0.y;
        a1.x += f1.x; a1.y += f1.y;
    }
    const int vd = 2 * (voff + lane);
    *(float2*)&ctx[(size_t)(b * LK + k0 + kp2)     * VD + vd] = a0;
    *(float2*)&ctx[(size_t)(b * LK + k0 + kp2 + 1) * VD + vd] = a1;
}

// ============================================================================
// Launch: inputs: query, key, value, Wq, Wk, v
// d_out = context [B,LK,VD] followed by attention [B,LK,LQ]
// ============================================================================
extern "C" void kernel_launch(void* const* d_in, const int* in_sizes, int n_in,
                              void* d_out, int out_size)
{
    const float* query = (const float*)d_in[0];
    const float* key_t = (const float*)d_in[1];
    const float* value = (const float*)d_in[2];
    const float* Wq    = (const float*)d_in[3];
    const float* Wk    = (const float*)d_in[4];
    const float* vvec  = (const float*)d_in[5];

    float* ctx  = (float*)d_out;
    float* attn = ctx + (size_t)B_ * LK * VD;

    cudaMemcpyToSymbolAsync(c_vvec, vvec, HD * sizeof(float), 0,
                            cudaMemcpyDeviceToDevice);
    cvt_val_kernel<<<256, 256>>>(value);
    dim3 g1((B_ * LQ) / 32, 2);          // 256 CTAs
    proj_kernel<<<g1, 256>>>(query, key_t, Wq, Wk);
    attn_kernel<<<B_ * (LK / KT), 128>>>(ctx, attn);
}

// round 16
// speedup vs baseline: 1.1921x; 1.0040x over previous
#include <cuda_runtime.h>
#include <cuda_fp16.h>
#include <cuda_bf16.h>

#define B_  16
#define LQ  256
#define LK  256
#define QD  256
#define HD  128
#define VD  128
#define KT  4     // k-rows per CTA; every warp computes all 4 for its 64-q strip

// v vector in __constant__ memory (uniform per h; populated per launch via
// cudaMemcpyToSymbolAsync -- device-to-device, graph-capturable).
__constant__ float c_vvec[HD];

// f16 projected q/k, TRANSPOSED per batch: [b][h][q] / [b][h][k]  (2MB: L2-resident)
__device__ __half g_qpT[B_ * HD * LQ];
__device__ __half g_kpT[B_ * HD * LK];
__device__ __half g_val16[B_ * LQ * VD];   // f16 copy of value (1MB)

namespace {  // internal linkage: immune to cuda_fp16.hpp name collisions

__device__ __forceinline__ __half2 tanh_h2_(__half2 x) {
    unsigned xo, xi = *(unsigned*)&x;
    asm("tanh.approx.f16x2 %0, %1;" : "=r"(xo) : "r"(xi));
    return *(__half2*)&xo;
}
__device__ __forceinline__ unsigned long long pk2_(float lo, float hi) {
    unsigned long long r;
    asm("mov.b64 %0, {%1, %2};" : "=l"(r) : "f"(lo), "f"(hi));
    return r;
}
__device__ __forceinline__ void upk2_(unsigned long long v, float& lo, float& hi) {
    asm("mov.b64 {%0, %1}, %2;" : "=f"(lo), "=f"(hi) : "l"(v));
}
__device__ __forceinline__ void fma2_(unsigned long long& d, unsigned long long a,
                                      unsigned long long b) {
    asm("fma.rn.f32x2 %0, %1, %2, %0;" : "+l"(d) : "l"(a), "l"(b));
}

}  // namespace

// ============================================================================
// Kernel 1: grid (128, 3), 256 threads.
//   y==0: qp = query @ Wq   (BM=32, BN=128, BK=32, f32x2 FFMA; f16T epilogue)
//   y==1: kp = key   @ Wk   (same)
//   y==2: value f32 -> f16 g_val16 (mem-bound; overlaps the FFMA-bound CTAs)
// ============================================================================
__global__ __launch_bounds__(256) void proj_kernel(
    const float* __restrict__ q_in, const float* __restrict__ k_in,
    const float* __restrict__ Wq,   const float* __restrict__ Wk,
    const float* __restrict__ value)
{
    const int t = threadIdx.x;

    if (blockIdx.y == 2) {   // value conversion: 128 CTAs x 256 thr x 16 elems
        int i = (blockIdx.x * 256 + t) * 16;
        #pragma unroll
        for (int half = 0; half < 2; half++) {
            float4 a = *(const float4*)(value + i + half * 8);
            float4 b = *(const float4*)(value + i + half * 8 + 4);
            __half2 h0 = __floats2half2_rn(a.x, a.y), h1 = __floats2half2_rn(a.z, a.w);
            __half2 h2 = __floats2half2_rn(b.x, b.y), h3 = __floats2half2_rn(b.z, b.w);
            *(uint4*)&g_val16[i + half * 8] =
                make_uint4(*(unsigned*)&h0, *(unsigned*)&h1,
                           *(unsigned*)&h2, *(unsigned*)&h3);
        }
        return;
    }

    const float* X  = blockIdx.y ? k_in : q_in;
    const float* W  = blockIdx.y ? Wk : Wq;
    __half*      YT = blockIdx.y ? g_kpT : g_qpT;

    __shared__ __align__(16) float As[32][36];
    __shared__ __align__(16) float Bs[32][128];

    const int tx = t & 31;
    const int ty = t >> 5;
    const int r0 = blockIdx.x * 32;

    unsigned long long acc[2][4];
    #pragma unroll
    for (int rp = 0; rp < 2; rp++)
        #pragma unroll
        for (int c = 0; c < 4; c++) acc[rp][c] = 0ull;

    for (int kb = 0; kb < QD; kb += 32) {
        __syncthreads();
        {   // A tile 32x32 transposed
            int kk4 = t & 7, r = t >> 3;
            float4 a4 = *(const float4*)&X[(r0 + r) * QD + kb + kk4 * 4];
            As[kk4 * 4 + 0][r] = a4.x;
            As[kk4 * 4 + 1][r] = a4.y;
            As[kk4 * 4 + 2][r] = a4.z;
            As[kk4 * 4 + 3][r] = a4.w;
        }
        {   // B tile 32x128
            int h4 = t & 31, kk = t >> 5;
            #pragma unroll
            for (int j = 0; j < 4; j++)
                *(float4*)&Bs[kk + 8 * j][h4 * 4] =
                    *(const float4*)&W[(kb + kk + 8 * j) * HD + h4 * 4];
        }
        __syncthreads();
        #pragma unroll
        for (int kk = 0; kk < 32; kk++) {
            float4 a  = *(const float4*)&As[kk][ty * 4];
            float4 bv = *(const float4*)&Bs[kk][tx * 4];
            unsigned long long ap0 = pk2_(a.x, a.y);
            unsigned long long ap1 = pk2_(a.z, a.w);
            unsigned long long bb[4] = { pk2_(bv.x, bv.x), pk2_(bv.y, bv.y),
                                         pk2_(bv.z, bv.z), pk2_(bv.w, bv.w) };
            #pragma unroll
            for (int c = 0; c < 4; c++) { fma2_(acc[0][c], ap0, bb[c]);
                                          fma2_(acc[1][c], ap1, bb[c]); }
        }
    }

    const int bb   = r0 / LQ;
    const int qloc = (r0 % LQ) + ty * 4;
    #pragma unroll
    for (int c = 0; c < 4; c++) {
        int h = tx * 4 + c;
        float r01lo, r01hi, r23lo, r23hi;
        upk2_(acc[0][c], r01lo, r01hi);
        upk2_(acc[1][c], r23lo, r23hi);
        __half2 p0 = __floats2half2_rn(r01lo, r01hi);
        __half2 p1 = __floats2half2_rn(r23lo, r23hi);
        uint2 out = make_uint2(*(unsigned*)&p0, *(unsigned*)&p1);
        *(uint2*)&YT[(bb * HD + h) * LQ + qloc] = out;
    }
}

// ============================================================================
// Kernel 2: scores + softmax + context. grid = 1024 CTAs, 128 threads.
// Phase B (R12): no smem. Warp w owns q-strip [64w,64w+64), lane=2 q.
// Phase C: softmax; attn written via STG.32; f16 P to S16h.
// Phase D: barrier-free, f16 HFMA2, value loads double-buffered (v_cur/v_nxt)
//   so ~16 LDGs are in flight instead of issue->consume lockstep.
// ============================================================================
__global__ __launch_bounds__(128, 7) void attn_kernel(
    float* __restrict__ ctx, float* __restrict__ attn)
{
    const int b  = blockIdx.x >> 6;          // 64 k-tiles per batch
    const int k0 = (blockIdx.x & 63) * KT;

    __shared__ __align__(16) float  S[4 * 256];      // 4096 B (scores)
    __shared__ __align__(8)  __half S16h[4 * 256];   // 2048 B (P f16)

    const int t    = threadIdx.x;
    const int w    = t >> 5;
    const int lane = t & 31;
    const int qidx = w * 32 + lane;          // q = 2*qidx, 2*qidx+1

    const __half* qb = g_qpT + (size_t)b * HD * LQ + 2 * qidx;
    const __half* kb = g_kpT + (size_t)b * HD * LK + k0;

    float accf[4][2];
    #pragma unroll
    for (int k = 0; k < 4; k++) { accf[k][0] = 0.f; accf[k][1] = 0.f; }

    // ---- Phase B: scores, straight from gmem (L2-resident) ----
    #pragma unroll 2
    for (int h8 = 0; h8 < HD; h8 += 8) {
        unsigned qv[8]; uint2 kp[8];
        #pragma unroll
        for (int j = 0; j < 8; j++) {
            qv[j] = *(const unsigned*)(qb + (h8 + j) * LQ);   // lane-strided
            kp[j] = *(const uint2*)  (kb + (h8 + j) * LK);    // uniform
        }
        __half2 ae[4], ao[4];
        #pragma unroll
        for (int k = 0; k < 4; k++) { ae[k] = __float2half2_rn(0.f); ao[k] = ae[k]; }
        #pragma unroll
        for (int j = 0; j < 8; j++) {
            __half2 q2   = *(__half2*)&qv[j];
            __half2 kp01 = *(__half2*)&kp[j].x;
            __half2 kp23 = *(__half2*)&kp[j].y;
            __half2 vd   = __float2half2_rn(c_vvec[h8 + j]);
            __half2 t0 = tanh_h2_(__hadd2(q2, __low2half2(kp01)));
            __half2 t1 = tanh_h2_(__hadd2(q2, __high2half2(kp01)));
            __half2 t2 = tanh_h2_(__hadd2(q2, __low2half2(kp23)));
            __half2 t3 = tanh_h2_(__hadd2(q2, __high2half2(kp23)));
            if (j & 1) {
                ao[0] = __hfma2(t0, vd, ao[0]); ao[1] = __hfma2(t1, vd, ao[1]);
                ao[2] = __hfma2(t2, vd, ao[2]); ao[3] = __hfma2(t3, vd, ao[3]);
            } else {
                ae[0] = __hfma2(t0, vd, ae[0]); ae[1] = __hfma2(t1, vd, ae[1]);
                ae[2] = __hfma2(t2, vd, ae[2]); ae[3] = __hfma2(t3, vd, ae[3]);
            }
        }
        #pragma unroll
        for (int k = 0; k < 4; k++) {
            float2 f2 = __half22float2(__hadd2(ae[k], ao[k]));
            accf[k][0] += f2.x;
            accf[k][1] += f2.y;
        }
    }

    // ---- Phase C: softmax over q (scores -> S, warp w reduces k-row w) ----
    #pragma unroll
    for (int k = 0; k < 4; k++)
        *(float2*)&S[k * 256 + 2 * qidx] = make_float2(accf[k][0], accf[k][1]);
    __syncthreads();
    {
        float vals[8], m = -1e30f;
        #pragma unroll
        for (int i = 0; i < 8; i++) {
            vals[i] = S[w * 256 + lane + 32 * i];
            m = fmaxf(m, vals[i]);
        }
        #pragma unroll
        for (int o = 16; o > 0; o >>= 1)
            m = fmaxf(m, __shfl_xor_sync(0xffffffffu, m, o));
        float s = 0.f;
        #pragma unroll
        for (int i = 0; i < 8; i++) { vals[i] = __expf(vals[i] - m); s += vals[i]; }
        #pragma unroll
        for (int o = 16; o > 0; o >>= 1)
            s += __shfl_xor_sync(0xffffffffu, s, o);
        float inv = 1.0f / s;
        float* arow = attn + (size_t)(b * LK + k0 + w) * LQ;
        #pragma unroll
        for (int i = 0; i < 8; i++) {
            float p = vals[i] * inv;
            arow[lane + 32 * i] = p;                      // STG.32 coalesced
            S16h[w * 256 + lane + 32 * i] = __float2half(p);
        }
    }
    __syncthreads();                       // S16h visible to all warps

    // ---- Phase D: ctx = P @ value, barrier-free, f16 math, v double-buffered ----
    const int kp2  = (w & 1) * 2;
    const int voff = (w >> 1) * 32;        // half2 column index
    const __half* vb = g_val16 + (size_t)b * LQ * VD + 2 * (voff + lane);
    float2 a0 = make_float2(0.f, 0.f), a1 = a0;

    __half2 v_cur[8], v_nxt[8];
    #pragma unroll
    for (int j = 0; j < 8; j++)
        v_cur[j] = *(const __half2*)(vb + j * VD);

    #pragma unroll 2
    for (int q8 = 0; q8 < LQ; q8 += 8) {
        if (q8 + 8 < LQ) {
            #pragma unroll
            for (int j = 0; j < 8; j++)
                v_nxt[j] = *(const __half2*)(vb + (q8 + 8 + j) * VD);
        }
        __half2 e0 = __float2half2_rn(0.f), o0 = e0, e1 = e0, o1 = e0;
        #pragma unroll
        for (int q4 = 0; q4 < 2; q4++) {
            int q = q8 + q4 * 4;
            uint2 pu0 = *(const uint2*)&S16h[kp2 * 256 + q];        // bcast
            uint2 pu1 = *(const uint2*)&S16h[(kp2 + 1) * 256 + q];  // bcast
            __half2 p0ab = *(__half2*)&pu0.x, p0cd = *(__half2*)&pu0.y;
            __half2 p1ab = *(__half2*)&pu1.x, p1cd = *(__half2*)&pu1.y;
            __half2 v0 = v_cur[q4 * 4 + 0];
            __half2 v1 = v_cur[q4 * 4 + 1];
            __half2 v2 = v_cur[q4 * 4 + 2];
            __half2 v3 = v_cur[q4 * 4 + 3];
            e0 = __hfma2(v0, __low2half2(p0ab),  e0);
            e1 = __hfma2(v0, __low2half2(p1ab),  e1);
            o0 = __hfma2(v1, __high2half2(p0ab), o0);
            o1 = __hfma2(v1, __high2half2(p1ab), o1);
            e0 = __hfma2(v2, __low2half2(p0cd),  e0);
            e1 = __hfma2(v2, __low2half2(p1cd),  e1);
            o0 = __hfma2(v3, __high2half2(p0cd), o0);
            o1 = __hfma2(v3, __high2half2(p1cd), o1);
        }
        float2 f0 = __half22float2(__hadd2(e0, o0));
        float2 f1 = __half22float2(__hadd2(e1, o1));
        a0.x += f0.x; a0.y += f0.y;
        a1.x += f1.x; a1.y += f1.y;
        #pragma unroll
        for (int j = 0; j < 8; j++) v_cur[j] = v_nxt[j];
    }
    const int vd = 2 * (voff + lane);
    *(float2*)&ctx[(size_t)(b * LK + k0 + kp2)     * VD + vd] = a0;
    *(float2*)&ctx[(size_t)(b * LK + k0 + kp2 + 1) * VD + vd] = a1;
}

// ============================================================================
// Launch: inputs: query, key, value, Wq, Wk, v
// d_out = context [B,LK,VD] followed by attention [B,LK,LQ]
// ============================================================================
extern "C" void kernel_launch(void* const* d_in, const int* in_sizes, int n_in,
                              void* d_out, int out_size)
{
    const float* query = (const float*)d_in[0];
    const float* key_t = (const float*)d_in[1];
    const float* value = (const float*)d_in[2];
    const float* Wq    = (const float*)d_in[3];
    const float* Wk    = (const float*)d_in[4];
    const float* vvec  = (const float*)d_in[5];

    float* ctx  = (float*)d_out;
    float* attn = ctx + (size_t)B_ * LK * VD;

    cudaMemcpyToSymbolAsync(c_vvec, vvec, HD * sizeof(float), 0,
                            cudaMemcpyDeviceToDevice);
    dim3 g1((B_ * LQ) / 32, 3);          // 128 x 3: q-proj, k-proj, value-cvt
    proj_kernel<<<g1, 256>>>(query, key_t, Wq, Wk, value);
    attn_kernel<<<B_ * (LK / KT), 128>>>(ctx, attn);
}